// round 13
// baseline (speedup 1.0000x reference)
#include <cuda_runtime.h>
#include <cuda_fp16.h>
#include <cstdint>

#define B_  2
#define T_  4096
#define D_  1024
#define H_  16
#define DH_ 64
#define KP_ 4
#define TP_ 1024
#define NSPLIT 4

// ---------------- scratch (device globals; no allocations allowed) ----------
__device__ __half g_hs[(size_t)B_ * T_ * D_];
__device__ __half g_pool[B_ * TP_ * D_];
__device__ __half g_Wq[D_ * D_], g_Wk[D_ * D_], g_Wv[D_ * D_];
__device__ __half g_Qhi[(size_t)B_ * H_ * T_ * DH_];   // [B,H,T,DH], pre-scaled 1/8
__device__ __half g_Qlo[(size_t)B_ * H_ * T_ * DH_];
__device__ __half g_Khi[(size_t)B_ * H_ * TP_ * DH_];  // rows in [cnt, ceil64(cnt)) zeroed
__device__ __half g_Klo[(size_t)B_ * H_ * TP_ * DH_];
__device__ __half g_Vhi[(size_t)B_ * H_ * TP_ * DH_];
__device__ __half g_Vlo[(size_t)B_ * H_ * TP_ * DH_];
__device__ float g_KVp[(size_t)NSPLIT * 2 * B_ * H_ * TP_ * DH_];
__device__ int   g_act[B_ * TP_];
__device__ int   g_cnt[B_];

// ---------------- helpers ----------------------------------------------------
__device__ __forceinline__ uint32_t smem_u32(const void* p) {
    uint32_t a;
    asm("{ .reg .u64 t; cvta.to.shared.u64 t, %1; cvt.u32.u64 %0, t; }" : "=r"(a) : "l"(p));
    return a;
}
#define CP_ASYNC16(dst, src) \
    asm volatile("cp.async.cg.shared.global [%0], [%1], 16;" :: "r"(dst), "l"(src))
#define CP_COMMIT() asm volatile("cp.async.commit_group;" ::: "memory")

__device__ __forceinline__ void mma_f16(float* c,
        uint32_t a0, uint32_t a1, uint32_t a2, uint32_t a3,
        uint32_t b0, uint32_t b1) {
    asm volatile("mma.sync.aligned.m16n8k16.row.col.f32.f16.f16.f32 "
        "{%0,%1,%2,%3}, {%4,%5,%6,%7}, {%8,%9}, {%0,%1,%2,%3};"
        : "+f"(c[0]), "+f"(c[1]), "+f"(c[2]), "+f"(c[3])
        : "r"(a0), "r"(a1), "r"(a2), "r"(a3), "r"(b0), "r"(b1));
}
__device__ __forceinline__ void ldsm_x4(uint32_t* r, uint32_t addr) {
    asm volatile("ldmatrix.sync.aligned.m8n8.x4.shared.b16 {%0,%1,%2,%3}, [%4];"
        : "=r"(r[0]), "=r"(r[1]), "=r"(r[2]), "=r"(r[3]) : "r"(addr));
}
__device__ __forceinline__ void ldsm_x4t(uint32_t* r, uint32_t addr) {
    asm volatile("ldmatrix.sync.aligned.m8n8.x4.trans.shared.b16 {%0,%1,%2,%3}, [%4];"
        : "=r"(r[0]), "=r"(r[1]), "=r"(r[2]), "=r"(r[3]) : "r"(addr));
}
__device__ __forceinline__ uint32_t packh2(__half x, __half y) {
    __half2 v = __halves2half2(x, y);
    return *(uint32_t*)&v;
}

// ---------------- 1) fused weight fp16 conversion + hs/pool fp16 -------------
#define W4_ (D_ * D_ / 4)
#define HS4_ (B_ * TP_ * D_ / 4)
__global__ void prep_kernel(const float* __restrict__ hs,
                            const float* __restrict__ Wq,
                            const float* __restrict__ Wk,
                            const float* __restrict__ Wv) {
    int p = blockIdx.x * blockDim.x + threadIdx.x;
    if (p < 3 * W4_) {
        const float* src;
        __half* dst;
        int seg = p / W4_, off = p - seg * W4_;
        if (seg == 0)      { src = Wq; dst = g_Wq; }
        else if (seg == 1) { src = Wk; dst = g_Wk; }
        else               { src = Wv; dst = g_Wv; }
        float4 v = ((const float4*)src)[off];
        ushort4 h;
        h.x = __half_as_ushort(__float2half_rn(v.x));
        h.y = __half_as_ushort(__float2half_rn(v.y));
        h.z = __half_as_ushort(__float2half_rn(v.z));
        h.w = __half_as_ushort(__float2half_rn(v.w));
        ((ushort4*)dst)[off] = h;
        return;
    }
    p -= 3 * W4_;
    int d4  = p & 255;
    int row = p >> 8;
    const float4* src = (const float4*)hs;
    size_t base = (size_t)row * (KP_ * 256) + d4;
    float4 s[4];
    #pragma unroll
    for (int r = 0; r < 4; r++) s[r] = src[base + r * 256];
    #pragma unroll
    for (int r = 0; r < 4; r++) {
        ushort4 h;
        h.x = __half_as_ushort(__float2half_rn(s[r].x));
        h.y = __half_as_ushort(__float2half_rn(s[r].y));
        h.z = __half_as_ushort(__float2half_rn(s[r].z));
        h.w = __half_as_ushort(__float2half_rn(s[r].w));
        ((ushort4*)g_hs)[base + r * 256] = h;
    }
    ushort4 h;
    h.x = __half_as_ushort(__float2half_rn((s[0].x + s[1].x + s[2].x + s[3].x) * 0.25f));
    h.y = __half_as_ushort(__float2half_rn((s[0].y + s[1].y + s[2].y + s[3].y) * 0.25f));
    h.z = __half_as_ushort(__float2half_rn((s[0].z + s[1].z + s[2].z + s[3].z) * 0.25f));
    h.w = __half_as_ushort(__float2half_rn((s[0].w + s[1].w + s[2].w + s[3].w) * 0.25f));
    ((ushort4*)g_pool)[p] = h;
}

// ---------------- 2) mask -> compacted list (ballot scan, 2 barriers) --------
__global__ void mask_kernel(const int* __restrict__ am) {
    __shared__ int wsum[32];
    int b = blockIdx.x, tt = threadIdx.x;
    int lane = tt & 31, w = tt >> 5;
    const int* m = am + b * T_ + tt * KP_;
    int s = m[0] + m[1] + m[2] + m[3];
    int act = (s == 0) ? 1 : 0;
    unsigned bal = __ballot_sync(0xffffffffu, act);
    int wpre = __popc(bal & ((1u << lane) - 1u));
    if (lane == 31) wsum[w] = __popc(bal);
    __syncthreads();
    if (w == 0) {
        int v = wsum[lane];
        #pragma unroll
        for (int off = 1; off < 32; off <<= 1) {
            int u = __shfl_up_sync(0xffffffffu, v, off);
            if (lane >= off) v += u;
        }
        wsum[lane] = v;   // inclusive warp-sum scan
    }
    __syncthreads();
    int total = wsum[31];
    int pre = (w ? wsum[w - 1] : 0) + wpre;   // exclusive prefix of this thread
    if (total == 0) {
        g_act[b * TP_ + tt] = tt;
        if (tt == 0) g_cnt[b] = TP_;
    } else {
        if (act) g_act[b * TP_ + pre] = tt;
        if (tt >= total) g_act[b * TP_ + tt] = 0;
        if (tt == 0) g_cnt[b] = total;
    }
}

// ---------------- 3) fused fp16 projection GEMM (Q + split-K KV) -------------
#define RS_ 144
#define ARR_BYTES (128 * RS_)        // 18432
#define STAGE_BYTES (2 * ARR_BYTES)  // 36864
#define SMEM_GEMM (2 * STAGE_BYTES)  // 73728

__global__ void __launch_bounds__(256, 2)
gemm_fused_kernel(const float* __restrict__ bq_)
{
    extern __shared__ char smc[];
    const uint32_t sb = smem_u32(smc);
    const int tid = threadIdx.x;
    const int wid = tid >> 5, lane = tid & 31;

    int mode, bn, bm, batch = 0, kbase = 0, NK;
    const __half *A, *W;
    float* outp = nullptr;
    if (blockIdx.x < 512) {
        mode = 0;
        bn = (blockIdx.x & 7) * 128;
        bm = (blockIdx.x >> 3) * 128;
        A = g_hs; W = g_Wq;
        NK = D_ / 64;
    } else {
        mode = 1;
        int r = blockIdx.x - 512;
        bn = (r & 7) * 128;
        bm = ((r >> 3) & 7) * 128;
        int z = r >> 6;
        batch = z & 1;
        int sel = (z >> 1) & 1;
        int split = z >> 2;
        if (bm >= g_cnt[batch]) return;
        A = g_pool;
        W = sel ? g_Wv : g_Wk;
        outp = g_KVp + ((size_t)(split * 2 + sel) * B_ + batch) * ((size_t)H_ * TP_ * DH_);
        kbase = split * (D_ / NSPLIT);
        NK = (D_ / NSPLIT) / 64;
    }

    auto load_stage = [&](int kt, int stage) {
        const uint32_t sbase = sb + stage * STAGE_BYTES;
        const int koff = kbase + kt * 64;
        #pragma unroll
        for (int i = 0; i < 8; i++) {
            int idx = tid + i * 256;
            int arr = idx >> 10;
            int r = (idx >> 3) & 127;
            int c = idx & 7;
            const __half* src;
            if (arr == 0) {
                size_t row;
                if (mode == 0) row = (size_t)(bm + r);
                else row = (size_t)batch * TP_ + g_act[batch * TP_ + bm + r];
                src = A + row * D_ + koff + c * 8;
            } else {
                src = W + (size_t)(bn + r) * D_ + koff + c * 8;
            }
            CP_ASYNC16(sbase + arr * ARR_BYTES + r * RS_ + c * 16, src);
        }
        CP_COMMIT();
    };

    float acc[2][8][4];
    #pragma unroll
    for (int mt = 0; mt < 2; mt++)
        #pragma unroll
        for (int nt = 0; nt < 8; nt++)
            #pragma unroll
            for (int j = 0; j < 4; j++) acc[mt][nt][j] = 0.0f;

    const int wm = (wid & 3) * 32;
    const int wn = (wid >> 2) * 64;

    const int arw = (lane & 7) + ((lane >> 3) & 1) * 8;
    const int akh = lane >> 4;
    const int brw = (lane & 7) + (lane >> 4) * 8;
    const int bkh = (lane >> 3) & 1;
    const uint32_t aoff = (uint32_t)((wm + arw) * RS_ + akh * 16);
    const uint32_t boff = (uint32_t)(ARR_BYTES + (wn + brw) * RS_ + bkh * 16);

    load_stage(0, 0);

    for (int kt = 0; kt < NK; kt++) {
        if (kt + 1 < NK) {
            load_stage(kt + 1, (kt + 1) & 1);
            asm volatile("cp.async.wait_group 1;" ::: "memory");
        } else {
            asm volatile("cp.async.wait_group 0;" ::: "memory");
        }
        __syncthreads();

        const uint32_t st = sb + (kt & 1) * STAGE_BYTES;
        const uint32_t aB = st + aoff;
        const uint32_t bB = st + boff;

        #pragma unroll
        for (int j = 0; j < 4; j++) {
            uint32_t af[2][4];
            ldsm_x4(af[0], aB + j * 32);
            ldsm_x4(af[1], aB + 16 * RS_ + j * 32);
            #pragma unroll
            for (int np = 0; np < 4; np++) {
                uint32_t bw[4];
                ldsm_x4(bw, bB + np * 16 * RS_ + j * 32);
                #pragma unroll
                for (int s = 0; s < 2; s++) {
                    const int nt = 2 * np + s;
                    #pragma unroll
                    for (int mt = 0; mt < 2; mt++)
                        mma_f16(acc[mt][nt], af[mt][0], af[mt][1], af[mt][2], af[mt][3], bw[2*s], bw[2*s+1]);
                }
            }
        }
        __syncthreads();
    }

    // ---- epilogue ----
    const int lr = lane >> 2;
    const int lc = (lane & 3) * 2;
    #pragma unroll
    for (int nt = 0; nt < 8; nt++) {
        int c0 = bn + wn + (nt >> 1) * 16 + (nt & 1) * 8 + lc;
        int h = c0 >> 6, d0 = c0 & 63;
        float2 b2 = make_float2(0.0f, 0.0f);
        if (mode == 0) b2 = *(const float2*)(bq_ + c0);
        #pragma unroll
        for (int mt = 0; mt < 2; mt++) {
            int m0 = bm + wm + mt * 16 + lr;
            #pragma unroll
            for (int half = 0; half < 2; half++) {
                int m = m0 + half * 8;
                if (mode == 0) {
                    int b = m >> 12, ls = m & (T_ - 1);
                    size_t dst = ((size_t)(b * H_ + h) * T_ + ls) * DH_ + d0;
                    float sx = (acc[mt][nt][2 * half + 0] + b2.x) * 0.125f;
                    float sy = (acc[mt][nt][2 * half + 1] + b2.y) * 0.125f;
                    __half hx = __float2half_rn(sx), hy = __float2half_rn(sy);
                    __half lx = __float2half_rn(sx - __half2float(hx));
                    __half ly = __float2half_rn(sy - __half2float(hy));
                    *(uint32_t*)(g_Qhi + dst) = packh2(hx, hy);
                    *(uint32_t*)(g_Qlo + dst) = packh2(lx, ly);
                } else {
                    size_t dst = ((size_t)h * TP_ + m) * DH_ + d0;
                    float2 o;
                    o.x = acc[mt][nt][2 * half + 0];
                    o.y = acc[mt][nt][2 * half + 1];
                    *(float2*)(outp + dst) = o;
                }
            }
        }
    }
}

// ---------------- 4) split-K reduce + bias -> K/V fp16 hi/lo -----------------
// Only rows < ceil64(cnt) matter (attention never reads beyond); rows in
// [cnt, ceil64(cnt)) are zero-filled, everything above exits immediately.
__global__ void kv_reduce_kernel(const float* __restrict__ bk,
                                 const float* __restrict__ bv) {
    int p = blockIdx.x * blockDim.x + threadIdx.x;
    int d4  = p & 15;
    int i   = (p >> 4) & (TP_ - 1);
    int h   = (p >> 14) & (H_ - 1);
    int b   = (p >> 18) & (B_ - 1);
    int sel = (p >> 19) & 1;
    const int cnt = g_cnt[b];
    const int cnt64 = (cnt + 63) & ~63;
    if (i >= cnt64) return;
    size_t dsti = ((size_t)(b * H_ + h) * TP_ + i) * DH_ + d4 * 4;
    __half* outh = sel ? g_Vhi : g_Khi;
    __half* outl = sel ? g_Vlo : g_Klo;
    if (i >= cnt) {
        *(uint2*)(outh + dsti) = make_uint2(0u, 0u);
        *(uint2*)(outl + dsti) = make_uint2(0u, 0u);
        return;
    }
    float4 acc = make_float4(0.f, 0.f, 0.f, 0.f);
    #pragma unroll
    for (int sp = 0; sp < NSPLIT; sp++) {
        const float* base = g_KVp
            + ((size_t)(sp * 2 + sel) * B_ + b) * ((size_t)H_ * TP_ * DH_)
            + ((size_t)h * TP_ + i) * DH_;
        float4 v = ((const float4*)base)[d4];
        acc.x += v.x; acc.y += v.y; acc.z += v.z; acc.w += v.w;
    }
    const float* bias = sel ? bv : bk;
    float4 bb = ((const float4*)(bias + h * DH_))[d4];
    acc.x += bb.x; acc.y += bb.y; acc.z += bb.z; acc.w += bb.w;
    __half hx = __float2half_rn(acc.x), hy = __float2half_rn(acc.y);
    __half hz = __float2half_rn(acc.z), hw = __float2half_rn(acc.w);
    uint2 hv, lv;
    hv.x = packh2(hx, hy); hv.y = packh2(hz, hw);
    lv.x = packh2(__float2half_rn(acc.x - __half2float(hx)),
                  __float2half_rn(acc.y - __half2float(hy)));
    lv.y = packh2(__float2half_rn(acc.z - __half2float(hz)),
                  __float2half_rn(acc.w - __half2float(hw)));
    *(uint2*)(outh + dsti) = hv;
    *(uint2*)(outl + dsti) = lv;
}

// ---------------- 5) fp16 tensor-core flash attention (128 q / block) --------
// 256 threads, 8 warps x 16 q rows. Q hi/lo [128][64], KV hi/lo [64][64].
#define ATS 144
#define QARR (128 * ATS)     // 18432
#define KVARR (64 * ATS)     // 9216
#define SM_KH (2 * QARR)                 // 36864
#define SM_VH (SM_KH + 2 * KVARR)        // 55296
#define SMEM_ATTN (SM_VH + 2 * KVARR)    // 73728

__global__ void __launch_bounds__(256, 2)
attn_kernel(float* __restrict__ out)
{
    extern __shared__ char smc[];
    const uint32_t sb = smem_u32(smc);
    const int tid = threadIdx.x, wid = tid >> 5, lane = tid & 31;
    const int b = blockIdx.z, h = blockIdx.y, q0 = blockIdx.x * 128;
    const int cnt = g_cnt[b];
    const int ntiles = (cnt + 63) >> 6;

    const __half* Qhp = g_Qhi + ((size_t)(b * H_ + h) * T_ + q0) * DH_;
    const __half* Qlp = g_Qlo + ((size_t)(b * H_ + h) * T_ + q0) * DH_;
    const size_t kvoff = (size_t)(b * H_ + h) * TP_ * DH_;
    const __half* kvsrc[4] = { g_Khi + kvoff, g_Klo + kvoff,
                               g_Vhi + kvoff, g_Vlo + kvoff };

    // load Q tiles: 2 arrays x 128 rows x 8 chunks = 2048 chunks / 256 thr
    #pragma unroll
    for (int i = 0; i < 8; i++) {
        int idx = tid + i * 256;
        int arr = idx >> 10, r = (idx >> 3) & 127, c = idx & 7;
        const __half* src = (arr ? Qlp : Qhp) + (size_t)r * DH_ + c * 8;
        CP_ASYNC16(sb + arr * QARR + r * ATS + c * 16, src);
    }
    CP_COMMIT();

    float acc[8][4];
    #pragma unroll
    for (int nt = 0; nt < 8; nt++)
        #pragma unroll
        for (int j = 0; j < 4; j++) acc[nt][j] = 0.0f;
    float mrow[2] = { -1e30f, -1e30f };
    float lrow[2] = { 0.0f, 0.0f };

    const int lr = lane >> 2, lq = lane & 3;
    const int arw = (lane & 7) + ((lane >> 3) & 1) * 8;
    const int akh = lane >> 4;
    const int brw = (lane & 7) + (lane >> 4) * 8;
    const int bkh = (lane >> 3) & 1;
    const int vrw = (lane & 7) + ((lane >> 3) & 1) * 8;
    const int vc16 = (lane >> 4) * 16;

    const uint32_t qbase = sb + (wid * 16 + arw) * ATS + akh * 16;
    const uint32_t kbase = sb + SM_KH + brw * ATS + bkh * 16;
    const uint32_t vbase = sb + SM_VH + vrw * ATS + vc16;

    for (int t = 0; t < ntiles; t++) {
        const int kb = t * 64;
        // KV tiles: 4 arrays x 64 rows x 8 chunks = 2048 chunks / 256 thr
        #pragma unroll
        for (int i = 0; i < 8; i++) {
            int idx = tid + i * 256;
            int arr = idx >> 9, r = (idx >> 3) & 63, c = idx & 7;
            CP_ASYNC16(sb + SM_KH + arr * KVARR + r * ATS + c * 16,
                       kvsrc[arr] + (size_t)(kb + r) * DH_ + c * 8);
        }
        CP_COMMIT();
        asm volatile("cp.async.wait_group 0;" ::: "memory");
        __syncthreads();

        // ---- scores: 3-pass QhKh + QhKl + QlKh ----
        float sc[8][4];
        #pragma unroll
        for (int nt = 0; nt < 8; nt++)
            #pragma unroll
            for (int j = 0; j < 4; j++) sc[nt][j] = 0.0f;
        #pragma unroll
        for (int j = 0; j < 4; j++) {
            uint32_t qh[4], ql[4];
            ldsm_x4(qh, qbase + j * 32);
            ldsm_x4(ql, qbase + QARR + j * 32);
            #pragma unroll
            for (int np = 0; np < 4; np++) {
                uint32_t kh4[4], kl4[4];
                ldsm_x4(kh4, kbase + np * 16 * ATS + j * 32);
                ldsm_x4(kl4, kbase + KVARR + np * 16 * ATS + j * 32);
                #pragma unroll
                for (int s = 0; s < 2; s++) {
                    const int nt = 2 * np + s;
                    mma_f16(sc[nt], qh[0], qh[1], qh[2], qh[3], kh4[2*s], kh4[2*s+1]);
                    mma_f16(sc[nt], qh[0], qh[1], qh[2], qh[3], kl4[2*s], kl4[2*s+1]);
                    mma_f16(sc[nt], ql[0], ql[1], ql[2], ql[3], kh4[2*s], kh4[2*s+1]);
                }
            }
        }

        #pragma unroll
        for (int nt = 0; nt < 8; nt++) {
            int key = kb + nt * 8 + lq * 2;
            if (key >= cnt)     { sc[nt][0] = -1e30f; sc[nt][2] = -1e30f; }
            if (key + 1 >= cnt) { sc[nt][1] = -1e30f; sc[nt][3] = -1e30f; }
        }

        float tm0 = -1e30f, tm1 = -1e30f;
        #pragma unroll
        for (int nt = 0; nt < 8; nt++) {
            tm0 = fmaxf(tm0, fmaxf(sc[nt][0], sc[nt][1]));
            tm1 = fmaxf(tm1, fmaxf(sc[nt][2], sc[nt][3]));
        }
        tm0 = fmaxf(tm0, __shfl_xor_sync(0xffffffffu, tm0, 1));
        tm0 = fmaxf(tm0, __shfl_xor_sync(0xffffffffu, tm0, 2));
        tm1 = fmaxf(tm1, __shfl_xor_sync(0xffffffffu, tm1, 1));
        tm1 = fmaxf(tm1, __shfl_xor_sync(0xffffffffu, tm1, 2));
        const float mn0 = fmaxf(mrow[0], tm0);
        const float mn1 = fmaxf(mrow[1], tm1);
        const float al0 = __expf(mrow[0] - mn0);
        const float al1 = __expf(mrow[1] - mn1);

        uint32_t pAh[4][4], pAl[4][4];
        float ts0 = 0.0f, ts1 = 0.0f;
        #pragma unroll
        for (int nt = 0; nt < 8; nt++) {
            float p0 = __expf(sc[nt][0] - mn0);
            float p1 = __expf(sc[nt][1] - mn0);
            float p2 = __expf(sc[nt][2] - mn1);
            float p3 = __expf(sc[nt][3] - mn1);
            ts0 += p0 + p1;
            ts1 += p2 + p3;
            __half h0 = __float2half_rn(p0), h1 = __float2half_rn(p1);
            __half h2 = __float2half_rn(p2), h3 = __float2half_rn(p3);
            __half e0 = __float2half_rn(p0 - __half2float(h0));
            __half e1 = __float2half_rn(p1 - __half2float(h1));
            __half e2 = __float2half_rn(p2 - __half2float(h2));
            __half e3 = __float2half_rn(p3 - __half2float(h3));
            const int j = nt >> 1, o = (nt & 1) * 2;
            pAh[j][o]     = packh2(h0, h1);
            pAh[j][o + 1] = packh2(h2, h3);
            pAl[j][o]     = packh2(e0, e1);
            pAl[j][o + 1] = packh2(e2, e3);
        }
        ts0 += __shfl_xor_sync(0xffffffffu, ts0, 1);
        ts0 += __shfl_xor_sync(0xffffffffu, ts0, 2);
        ts1 += __shfl_xor_sync(0xffffffffu, ts1, 1);
        ts1 += __shfl_xor_sync(0xffffffffu, ts1, 2);
        lrow[0] = lrow[0] * al0 + ts0;
        lrow[1] = lrow[1] * al1 + ts1;
        mrow[0] = mn0;
        mrow[1] = mn1;
        #pragma unroll
        for (int nt = 0; nt < 8; nt++) {
            acc[nt][0] *= al0; acc[nt][1] *= al0;
            acc[nt][2] *= al1; acc[nt][3] *= al1;
        }

        // ---- P @ V : 3-pass PhVh + PhVl + PlVh ----
        #pragma unroll
        for (int j = 0; j < 4; j++) {
            #pragma unroll
            for (int np = 0; np < 4; np++) {
                uint32_t vh4[4], vl4[4];
                ldsm_x4t(vh4, vbase + (j * 16) * ATS + np * 32);
                ldsm_x4t(vl4, vbase + KVARR + (j * 16) * ATS + np * 32);
                #pragma unroll
                for (int s = 0; s < 2; s++) {
                    const int nt = 2 * np + s;
                    mma_f16(acc[nt], pAh[j][0], pAh[j][1], pAh[j][2], pAh[j][3], vh4[2*s], vh4[2*s+1]);
                    mma_f16(acc[nt], pAh[j][0], pAh[j][1], pAh[j][2], pAh[j][3], vl4[2*s], vl4[2*s+1]);
                    mma_f16(acc[nt], pAl[j][0], pAl[j][1], pAl[j][2], pAl[j][3], vh4[2*s], vh4[2*s+1]);
                }
            }
        }
        __syncthreads();
    }

    const float inv0 = 1.0f / lrow[0];
    const float inv1 = 1.0f / lrow[1];
    const int row0 = q0 + wid * 16 + lr;
    #pragma unroll
    for (int nt = 0; nt < 8; nt++) {
        int dh = nt * 8 + lq * 2;
        float2 o;
        o.x = acc[nt][0] * inv0; o.y = acc[nt][1] * inv0;
        *(float2*)(out + ((size_t)b * T_ + row0) * D_ + h * DH_ + dh) = o;
        o.x = acc[nt][2] * inv1; o.y = acc[nt][3] * inv1;
        *(float2*)(out + ((size_t)b * T_ + row0 + 8) * D_ + h * DH_ + dh) = o;
    }
}

// ---------------- launch -----------------------------------------------------
extern "C" void kernel_launch(void* const* d_in, const int* in_sizes, int n_in,
                              void* d_out, int out_size) {
    const float* hs = (const float*)d_in[0];
    const int*   am = (const int*)d_in[1];
    const float* Wq = (const float*)d_in[2];
    const float* bq = (const float*)d_in[3];
    const float* Wk = (const float*)d_in[4];
    const float* bk = (const float*)d_in[5];
    const float* Wv = (const float*)d_in[6];
    const float* bv = (const float*)d_in[7];
    float* out = (float*)d_out;

    cudaFuncSetAttribute(gemm_fused_kernel, cudaFuncAttributeMaxDynamicSharedMemorySize, SMEM_GEMM);
    cudaFuncSetAttribute(attn_kernel, cudaFuncAttributeMaxDynamicSharedMemorySize, SMEM_ATTN);

    prep_kernel<<<(3 * W4_ + HS4_) / 256, 256>>>(hs, Wq, Wk, Wv);
    mask_kernel<<<B_, TP_>>>(am);
    gemm_fused_kernel<<<512 + 1024, 256, SMEM_GEMM>>>(bq);
    kv_reduce_kernel<<<(2 * B_ * H_ * TP_ * (DH_ / 4)) / 256, 256>>>(bk, bv);
    attn_kernel<<<dim3(T_ / 128, H_, B_), 256, SMEM_ATTN>>>(out);
}

// round 14
// speedup vs baseline: 1.0424x; 1.0424x over previous
#include <cuda_runtime.h>
#include <cuda_fp16.h>
#include <cstdint>

#define B_  2
#define T_  4096
#define D_  1024
#define H_  16
#define DH_ 64
#define KP_ 4
#define TP_ 1024

// ---------------- scratch (device globals; no allocations allowed) ----------
__device__ __half g_hs[(size_t)B_ * T_ * D_];
__device__ __half g_pool[B_ * TP_ * D_];
__device__ __half g_Wq[D_ * D_], g_Wk[D_ * D_], g_Wv[D_ * D_];
__device__ __half g_Qhi[(size_t)B_ * H_ * T_ * DH_];   // [B,H,T,DH], pre-scaled 1/8
__device__ __half g_Qlo[(size_t)B_ * H_ * T_ * DH_];
__device__ __half g_Khi[(size_t)B_ * H_ * TP_ * DH_];  // rows in [cnt, block-cover) zeroed
__device__ __half g_Klo[(size_t)B_ * H_ * TP_ * DH_];
__device__ __half g_Vhi[(size_t)B_ * H_ * TP_ * DH_];
__device__ __half g_Vlo[(size_t)B_ * H_ * TP_ * DH_];
__device__ int   g_act[B_ * TP_];
__device__ int   g_cnt[B_];

// ---------------- helpers ----------------------------------------------------
__device__ __forceinline__ uint32_t smem_u32(const void* p) {
    uint32_t a;
    asm("{ .reg .u64 t; cvta.to.shared.u64 t, %1; cvt.u32.u64 %0, t; }" : "=r"(a) : "l"(p));
    return a;
}
#define CP_ASYNC16(dst, src) \
    asm volatile("cp.async.cg.shared.global [%0], [%1], 16;" :: "r"(dst), "l"(src))
#define CP_COMMIT() asm volatile("cp.async.commit_group;" ::: "memory")

__device__ __forceinline__ void mma_f16(float* c,
        uint32_t a0, uint32_t a1, uint32_t a2, uint32_t a3,
        uint32_t b0, uint32_t b1) {
    asm volatile("mma.sync.aligned.m16n8k16.row.col.f32.f16.f16.f32 "
        "{%0,%1,%2,%3}, {%4,%5,%6,%7}, {%8,%9}, {%0,%1,%2,%3};"
        : "+f"(c[0]), "+f"(c[1]), "+f"(c[2]), "+f"(c[3])
        : "r"(a0), "r"(a1), "r"(a2), "r"(a3), "r"(b0), "r"(b1));
}
__device__ __forceinline__ void ldsm_x4(uint32_t* r, uint32_t addr) {
    asm volatile("ldmatrix.sync.aligned.m8n8.x4.shared.b16 {%0,%1,%2,%3}, [%4];"
        : "=r"(r[0]), "=r"(r[1]), "=r"(r[2]), "=r"(r[3]) : "r"(addr));
}
__device__ __forceinline__ void ldsm_x4t(uint32_t* r, uint32_t addr) {
    asm volatile("ldmatrix.sync.aligned.m8n8.x4.trans.shared.b16 {%0,%1,%2,%3}, [%4];"
        : "=r"(r[0]), "=r"(r[1]), "=r"(r[2]), "=r"(r[3]) : "r"(addr));
}
__device__ __forceinline__ uint32_t packh2(__half x, __half y) {
    __half2 v = __halves2half2(x, y);
    return *(uint32_t*)&v;
}

// ---------------- 1) fused weight fp16 conversion + hs/pool fp16 -------------
#define W4_ (D_ * D_ / 4)
#define HS4_ (B_ * TP_ * D_ / 4)
__global__ void prep_kernel(const float* __restrict__ hs,
                            const float* __restrict__ Wq,
                            const float* __restrict__ Wk,
                            const float* __restrict__ Wv) {
    int p = blockIdx.x * blockDim.x + threadIdx.x;
    if (p < 3 * W4_) {
        const float* src;
        __half* dst;
        int seg = p / W4_, off = p - seg * W4_;
        if (seg == 0)      { src = Wq; dst = g_Wq; }
        else if (seg == 1) { src = Wk; dst = g_Wk; }
        else               { src = Wv; dst = g_Wv; }
        float4 v = ((const float4*)src)[off];
        ushort4 h;
        h.x = __half_as_ushort(__float2half_rn(v.x));
        h.y = __half_as_ushort(__float2half_rn(v.y));
        h.z = __half_as_ushort(__float2half_rn(v.z));
        h.w = __half_as_ushort(__float2half_rn(v.w));
        ((ushort4*)dst)[off] = h;
        return;
    }
    p -= 3 * W4_;
    int d4  = p & 255;
    int row = p >> 8;
    const float4* src = (const float4*)hs;
    size_t base = (size_t)row * (KP_ * 256) + d4;
    float4 s[4];
    #pragma unroll
    for (int r = 0; r < 4; r++) s[r] = src[base + r * 256];
    #pragma unroll
    for (int r = 0; r < 4; r++) {
        ushort4 h;
        h.x = __half_as_ushort(__float2half_rn(s[r].x));
        h.y = __half_as_ushort(__float2half_rn(s[r].y));
        h.z = __half_as_ushort(__float2half_rn(s[r].z));
        h.w = __half_as_ushort(__float2half_rn(s[r].w));
        ((ushort4*)g_hs)[base + r * 256] = h;
    }
    ushort4 h;
    h.x = __half_as_ushort(__float2half_rn((s[0].x + s[1].x + s[2].x + s[3].x) * 0.25f));
    h.y = __half_as_ushort(__float2half_rn((s[0].y + s[1].y + s[2].y + s[3].y) * 0.25f));
    h.z = __half_as_ushort(__float2half_rn((s[0].z + s[1].z + s[2].z + s[3].z) * 0.25f));
    h.w = __half_as_ushort(__float2half_rn((s[0].w + s[1].w + s[2].w + s[3].w) * 0.25f));
    ((ushort4*)g_pool)[p] = h;
}

// ---------------- 2) mask -> compacted list (ballot scan, 2 barriers) --------
__global__ void mask_kernel(const int* __restrict__ am) {
    __shared__ int wsum[32];
    int b = blockIdx.x, tt = threadIdx.x;
    int lane = tt & 31, w = tt >> 5;
    const int* m = am + b * T_ + tt * KP_;
    int s = m[0] + m[1] + m[2] + m[3];
    int act = (s == 0) ? 1 : 0;
    unsigned bal = __ballot_sync(0xffffffffu, act);
    int wpre = __popc(bal & ((1u << lane) - 1u));
    if (lane == 31) wsum[w] = __popc(bal);
    __syncthreads();
    if (w == 0) {
        int v = wsum[lane];
        #pragma unroll
        for (int off = 1; off < 32; off <<= 1) {
            int u = __shfl_up_sync(0xffffffffu, v, off);
            if (lane >= off) v += u;
        }
        wsum[lane] = v;
    }
    __syncthreads();
    int total = wsum[31];
    int pre = (w ? wsum[w - 1] : 0) + wpre;
    if (total == 0) {
        g_act[b * TP_ + tt] = tt;
        if (tt == 0) g_cnt[b] = TP_;
    } else {
        if (act) g_act[b * TP_ + pre] = tt;
        if (tt >= total) g_act[b * TP_ + tt] = 0;
        if (tt == 0) g_cnt[b] = total;
    }
}

// ---------------- 3) fused fp16 projection GEMM (Q + KV, no split-K) ---------
// k64 per stage, 2-stage cp.async, 64 HMMA per barrier window, RS 144B.
// Grid: [0,512) Q; [512,768) KV (bn 8 x bm 8 x {batch,sel} 4) with early-exit.
// KV epilogue: + bias, fp16 hi/lo split, zero rows >= cnt (covers attn reads).
#define RS_ 144
#define ARR_BYTES (128 * RS_)        // 18432
#define STAGE_BYTES (2 * ARR_BYTES)  // 36864
#define SMEM_GEMM (2 * STAGE_BYTES)  // 73728

__global__ void __launch_bounds__(256, 2)
gemm_fused_kernel(const float* __restrict__ bq_,
                  const float* __restrict__ bk_,
                  const float* __restrict__ bv_)
{
    extern __shared__ char smc[];
    const uint32_t sb = smem_u32(smc);
    const int tid = threadIdx.x;
    const int wid = tid >> 5, lane = tid & 31;

    int mode, bn, bm, batch = 0, sel = 0, cnt = 0;
    const __half *A, *W;
    const float* bias;
    if (blockIdx.x < 512) {
        mode = 0;
        bn = (blockIdx.x & 7) * 128;
        bm = (blockIdx.x >> 3) * 128;
        A = g_hs; W = g_Wq; bias = bq_;
    } else {
        mode = 1;
        int r = blockIdx.x - 512;      // 8 bn x 8 bm x 4 z
        bn = (r & 7) * 128;
        bm = ((r >> 3) & 7) * 128;
        int z = r >> 6;                // 0..3
        batch = z & 1;
        sel = z >> 1;
        cnt = g_cnt[batch];
        if (bm >= cnt) return;
        A = g_pool;
        W = sel ? g_Wv : g_Wk;
        bias = sel ? bv_ : bk_;
    }
    const int NK = D_ / 64;            // 16 for both modes

    auto load_stage = [&](int kt, int stage) {
        const uint32_t sbase = sb + stage * STAGE_BYTES;
        const int koff = kt * 64;
        #pragma unroll
        for (int i = 0; i < 8; i++) {
            int idx = tid + i * 256;
            int arr = idx >> 10;
            int r = (idx >> 3) & 127;
            int c = idx & 7;
            const __half* src;
            if (arr == 0) {
                size_t row;
                if (mode == 0) row = (size_t)(bm + r);
                else row = (size_t)batch * TP_ + g_act[batch * TP_ + bm + r];
                src = A + row * D_ + koff + c * 8;
            } else {
                src = W + (size_t)(bn + r) * D_ + koff + c * 8;
            }
            CP_ASYNC16(sbase + arr * ARR_BYTES + r * RS_ + c * 16, src);
        }
        CP_COMMIT();
    };

    float acc[2][8][4];
    #pragma unroll
    for (int mt = 0; mt < 2; mt++)
        #pragma unroll
        for (int nt = 0; nt < 8; nt++)
            #pragma unroll
            for (int j = 0; j < 4; j++) acc[mt][nt][j] = 0.0f;

    const int wm = (wid & 3) * 32;
    const int wn = (wid >> 2) * 64;

    const int arw = (lane & 7) + ((lane >> 3) & 1) * 8;
    const int akh = lane >> 4;
    const int brw = (lane & 7) + (lane >> 4) * 8;
    const int bkh = (lane >> 3) & 1;
    const uint32_t aoff = (uint32_t)((wm + arw) * RS_ + akh * 16);
    const uint32_t boff = (uint32_t)(ARR_BYTES + (wn + brw) * RS_ + bkh * 16);

    load_stage(0, 0);

    for (int kt = 0; kt < NK; kt++) {
        if (kt + 1 < NK) {
            load_stage(kt + 1, (kt + 1) & 1);
            asm volatile("cp.async.wait_group 1;" ::: "memory");
        } else {
            asm volatile("cp.async.wait_group 0;" ::: "memory");
        }
        __syncthreads();

        const uint32_t st = sb + (kt & 1) * STAGE_BYTES;
        const uint32_t aB = st + aoff;
        const uint32_t bB = st + boff;

        #pragma unroll
        for (int j = 0; j < 4; j++) {
            uint32_t af[2][4];
            ldsm_x4(af[0], aB + j * 32);
            ldsm_x4(af[1], aB + 16 * RS_ + j * 32);
            #pragma unroll
            for (int np = 0; np < 4; np++) {
                uint32_t bw[4];
                ldsm_x4(bw, bB + np * 16 * RS_ + j * 32);
                #pragma unroll
                for (int s = 0; s < 2; s++) {
                    const int nt = 2 * np + s;
                    #pragma unroll
                    for (int mt = 0; mt < 2; mt++)
                        mma_f16(acc[mt][nt], af[mt][0], af[mt][1], af[mt][2], af[mt][3], bw[2*s], bw[2*s+1]);
                }
            }
        }
        __syncthreads();
    }

    // ---- epilogue: + bias, fp16 hi/lo split, head-major scatter ----
    const int lr = lane >> 2;
    const int lc = (lane & 3) * 2;
    __half* outh = sel ? g_Vhi : g_Khi;
    __half* outl = sel ? g_Vlo : g_Klo;
    #pragma unroll
    for (int nt = 0; nt < 8; nt++) {
        int c0 = bn + wn + (nt >> 1) * 16 + (nt & 1) * 8 + lc;
        int h = c0 >> 6, d0 = c0 & 63;
        float2 b2 = *(const float2*)(bias + c0);
        #pragma unroll
        for (int mt = 0; mt < 2; mt++) {
            int m0 = bm + wm + mt * 16 + lr;
            #pragma unroll
            for (int half = 0; half < 2; half++) {
                int m = m0 + half * 8;
                if (mode == 0) {
                    int b = m >> 12, ls = m & (T_ - 1);
                    size_t dst = ((size_t)(b * H_ + h) * T_ + ls) * DH_ + d0;
                    float sx = (acc[mt][nt][2 * half + 0] + b2.x) * 0.125f;
                    float sy = (acc[mt][nt][2 * half + 1] + b2.y) * 0.125f;
                    __half hx = __float2half_rn(sx), hy = __float2half_rn(sy);
                    __half lx = __float2half_rn(sx - __half2float(hx));
                    __half ly = __float2half_rn(sy - __half2float(hy));
                    *(uint32_t*)(g_Qhi + dst) = packh2(hx, hy);
                    *(uint32_t*)(g_Qlo + dst) = packh2(lx, ly);
                } else {
                    size_t dst = ((size_t)(batch * H_ + h) * TP_ + m) * DH_ + d0;
                    float sx = acc[mt][nt][2 * half + 0] + b2.x;
                    float sy = acc[mt][nt][2 * half + 1] + b2.y;
                    if (m >= cnt) { sx = 0.0f; sy = 0.0f; }  // dead rows -> zeros
                    __half hx = __float2half_rn(sx), hy = __float2half_rn(sy);
                    __half lx = __float2half_rn(sx - __half2float(hx));
                    __half ly = __float2half_rn(sy - __half2float(hy));
                    *(uint32_t*)(outh + dst) = packh2(hx, hy);
                    *(uint32_t*)(outl + dst) = packh2(lx, ly);
                }
            }
        }
    }
}

// ---------------- 4) fp16 tensor-core flash attention (128 q / block) --------
#define ATS 144
#define QARR (128 * ATS)
#define KVARR (64 * ATS)
#define SM_KH (2 * QARR)
#define SM_VH (SM_KH + 2 * KVARR)
#define SMEM_ATTN (SM_VH + 2 * KVARR)    // 73728

__global__ void __launch_bounds__(256, 2)
attn_kernel(float* __restrict__ out)
{
    extern __shared__ char smc[];
    const uint32_t sb = smem_u32(smc);
    const int tid = threadIdx.x, wid = tid >> 5, lane = tid & 31;
    const int b = blockIdx.z, h = blockIdx.y, q0 = blockIdx.x * 128;
    const int cnt = g_cnt[b];
    const int ntiles = (cnt + 63) >> 6;

    const __half* Qhp = g_Qhi + ((size_t)(b * H_ + h) * T_ + q0) * DH_;
    const __half* Qlp = g_Qlo + ((size_t)(b * H_ + h) * T_ + q0) * DH_;
    const size_t kvoff = (size_t)(b * H_ + h) * TP_ * DH_;
    const __half* kvsrc[4] = { g_Khi + kvoff, g_Klo + kvoff,
                               g_Vhi + kvoff, g_Vlo + kvoff };

    #pragma unroll
    for (int i = 0; i < 8; i++) {
        int idx = tid + i * 256;
        int arr = idx >> 10, r = (idx >> 3) & 127, c = idx & 7;
        const __half* src = (arr ? Qlp : Qhp) + (size_t)r * DH_ + c * 8;
        CP_ASYNC16(sb + arr * QARR + r * ATS + c * 16, src);
    }
    CP_COMMIT();

    float acc[8][4];
    #pragma unroll
    for (int nt = 0; nt < 8; nt++)
        #pragma unroll
        for (int j = 0; j < 4; j++) acc[nt][j] = 0.0f;
    float mrow[2] = { -1e30f, -1e30f };
    float lrow[2] = { 0.0f, 0.0f };

    const int lr = lane >> 2, lq = lane & 3;
    const int arw = (lane & 7) + ((lane >> 3) & 1) * 8;
    const int akh = lane >> 4;
    const int brw = (lane & 7) + (lane >> 4) * 8;
    const int bkh = (lane >> 3) & 1;
    const int vrw = (lane & 7) + ((lane >> 3) & 1) * 8;
    const int vc16 = (lane >> 4) * 16;

    const uint32_t qbase = sb + (wid * 16 + arw) * ATS + akh * 16;
    const uint32_t kbase = sb + SM_KH + brw * ATS + bkh * 16;
    const uint32_t vbase = sb + SM_VH + vrw * ATS + vc16;

    for (int t = 0; t < ntiles; t++) {
        const int kb = t * 64;
        #pragma unroll
        for (int i = 0; i < 8; i++) {
            int idx = tid + i * 256;
            int arr = idx >> 9, r = (idx >> 3) & 63, c = idx & 7;
            CP_ASYNC16(sb + SM_KH + arr * KVARR + r * ATS + c * 16,
                       kvsrc[arr] + (size_t)(kb + r) * DH_ + c * 8);
        }
        CP_COMMIT();
        asm volatile("cp.async.wait_group 0;" ::: "memory");
        __syncthreads();

        float sc[8][4];
        #pragma unroll
        for (int nt = 0; nt < 8; nt++)
            #pragma unroll
            for (int j = 0; j < 4; j++) sc[nt][j] = 0.0f;
        #pragma unroll
        for (int j = 0; j < 4; j++) {
            uint32_t qh[4], ql[4];
            ldsm_x4(qh, qbase + j * 32);
            ldsm_x4(ql, qbase + QARR + j * 32);
            #pragma unroll
            for (int np = 0; np < 4; np++) {
                uint32_t kh4[4], kl4[4];
                ldsm_x4(kh4, kbase + np * 16 * ATS + j * 32);
                ldsm_x4(kl4, kbase + KVARR + np * 16 * ATS + j * 32);
                #pragma unroll
                for (int s = 0; s < 2; s++) {
                    const int nt = 2 * np + s;
                    mma_f16(sc[nt], qh[0], qh[1], qh[2], qh[3], kh4[2*s], kh4[2*s+1]);
                    mma_f16(sc[nt], qh[0], qh[1], qh[2], qh[3], kl4[2*s], kl4[2*s+1]);
                    mma_f16(sc[nt], ql[0], ql[1], ql[2], ql[3], kh4[2*s], kh4[2*s+1]);
                }
            }
        }

        #pragma unroll
        for (int nt = 0; nt < 8; nt++) {
            int key = kb + nt * 8 + lq * 2;
            if (key >= cnt)     { sc[nt][0] = -1e30f; sc[nt][2] = -1e30f; }
            if (key + 1 >= cnt) { sc[nt][1] = -1e30f; sc[nt][3] = -1e30f; }
        }

        float tm0 = -1e30f, tm1 = -1e30f;
        #pragma unroll
        for (int nt = 0; nt < 8; nt++) {
            tm0 = fmaxf(tm0, fmaxf(sc[nt][0], sc[nt][1]));
            tm1 = fmaxf(tm1, fmaxf(sc[nt][2], sc[nt][3]));
        }
        tm0 = fmaxf(tm0, __shfl_xor_sync(0xffffffffu, tm0, 1));
        tm0 = fmaxf(tm0, __shfl_xor_sync(0xffffffffu, tm0, 2));
        tm1 = fmaxf(tm1, __shfl_xor_sync(0xffffffffu, tm1, 1));
        tm1 = fmaxf(tm1, __shfl_xor_sync(0xffffffffu, tm1, 2));
        const float mn0 = fmaxf(mrow[0], tm0);
        const float mn1 = fmaxf(mrow[1], tm1);
        const float al0 = __expf(mrow[0] - mn0);
        const float al1 = __expf(mrow[1] - mn1);

        uint32_t pAh[4][4], pAl[4][4];
        float ts0 = 0.0f, ts1 = 0.0f;
        #pragma unroll
        for (int nt = 0; nt < 8; nt++) {
            float p0 = __expf(sc[nt][0] - mn0);
            float p1 = __expf(sc[nt][1] - mn0);
            float p2 = __expf(sc[nt][2] - mn1);
            float p3 = __expf(sc[nt][3] - mn1);
            ts0 += p0 + p1;
            ts1 += p2 + p3;
            __half h0 = __float2half_rn(p0), h1 = __float2half_rn(p1);
            __half h2 = __float2half_rn(p2), h3 = __float2half_rn(p3);
            __half e0 = __float2half_rn(p0 - __half2float(h0));
            __half e1 = __float2half_rn(p1 - __half2float(h1));
            __half e2 = __float2half_rn(p2 - __half2float(h2));
            __half e3 = __float2half_rn(p3 - __half2float(h3));
            const int j = nt >> 1, o = (nt & 1) * 2;
            pAh[j][o]     = packh2(h0, h1);
            pAh[j][o + 1] = packh2(h2, h3);
            pAl[j][o]     = packh2(e0, e1);
            pAl[j][o + 1] = packh2(e2, e3);
        }
        ts0 += __shfl_xor_sync(0xffffffffu, ts0, 1);
        ts0 += __shfl_xor_sync(0xffffffffu, ts0, 2);
        ts1 += __shfl_xor_sync(0xffffffffu, ts1, 1);
        ts1 += __shfl_xor_sync(0xffffffffu, ts1, 2);
        lrow[0] = lrow[0] * al0 + ts0;
        lrow[1] = lrow[1] * al1 + ts1;
        mrow[0] = mn0;
        mrow[1] = mn1;
        #pragma unroll
        for (int nt = 0; nt < 8; nt++) {
            acc[nt][0] *= al0; acc[nt][1] *= al0;
            acc[nt][2] *= al1; acc[nt][3] *= al1;
        }

        #pragma unroll
        for (int j = 0; j < 4; j++) {
            #pragma unroll
            for (int np = 0; np < 4; np++) {
                uint32_t vh4[4], vl4[4];
                ldsm_x4t(vh4, vbase + (j * 16) * ATS + np * 32);
                ldsm_x4t(vl4, vbase + KVARR + (j * 16) * ATS + np * 32);
                #pragma unroll
                for (int s = 0; s < 2; s++) {
                    const int nt = 2 * np + s;
                    mma_f16(acc[nt], pAh[j][0], pAh[j][1], pAh[j][2], pAh[j][3], vh4[2*s], vh4[2*s+1]);
                    mma_f16(acc[nt], pAh[j][0], pAh[j][1], pAh[j][2], pAh[j][3], vl4[2*s], vl4[2*s+1]);
                    mma_f16(acc[nt], pAl[j][0], pAl[j][1], pAl[j][2], pAl[j][3], vh4[2*s], vh4[2*s+1]);
                }
            }
        }
        __syncthreads();
    }

    const float inv0 = 1.0f / lrow[0];
    const float inv1 = 1.0f / lrow[1];
    const int row0 = q0 + wid * 16 + lr;
    #pragma unroll
    for (int nt = 0; nt < 8; nt++) {
        int dh = nt * 8 + lq * 2;
        float2 o;
        o.x = acc[nt][0] * inv0; o.y = acc[nt][1] * inv0;
        *(float2*)(out + ((size_t)b * T_ + row0) * D_ + h * DH_ + dh) = o;
        o.x = acc[nt][2] * inv1; o.y = acc[nt][3] * inv1;
        *(float2*)(out + ((size_t)b * T_ + row0 + 8) * D_ + h * DH_ + dh) = o;
    }
}

// ---------------- launch -----------------------------------------------------
extern "C" void kernel_launch(void* const* d_in, const int* in_sizes, int n_in,
                              void* d_out, int out_size) {
    const float* hs = (const float*)d_in[0];
    const int*   am = (const int*)d_in[1];
    const float* Wq = (const float*)d_in[2];
    const float* bq = (const float*)d_in[3];
    const float* Wk = (const float*)d_in[4];
    const float* bk = (const float*)d_in[5];
    const float* Wv = (const float*)d_in[6];
    const float* bv = (const float*)d_in[7];
    float* out = (float*)d_out;

    cudaFuncSetAttribute(gemm_fused_kernel, cudaFuncAttributeMaxDynamicSharedMemorySize, SMEM_GEMM);
    cudaFuncSetAttribute(attn_kernel, cudaFuncAttributeMaxDynamicSharedMemorySize, SMEM_ATTN);

    prep_kernel<<<(3 * W4_ + HS4_) / 256, 256>>>(hs, Wq, Wk, Wv);
    mask_kernel<<<B_, TP_>>>(am);
    gemm_fused_kernel<<<512 + 256, 256, SMEM_GEMM>>>(bq, bk, bv);
    attn_kernel<<<dim3(T_ / 128, H_, B_), 256, SMEM_ATTN>>>(out);
}

// round 16
// speedup vs baseline: 1.0943x; 1.0497x over previous
#include <cuda_runtime.h>
#include <cuda_fp16.h>
#include <cstdint>

#define B_  2
#define T_  4096
#define D_  1024
#define H_  16
#define DH_ 64
#define KP_ 4
#define TP_ 1024

// ---------------- scratch (device globals; no allocations allowed) ----------
__device__ __half g_hs[(size_t)B_ * T_ * D_];
__device__ __half g_pool[B_ * TP_ * D_];
__device__ __half g_Wq[D_ * D_], g_Wk[D_ * D_], g_Wv[D_ * D_];
__device__ __half g_Qhi[(size_t)B_ * H_ * T_ * DH_];   // [B,H,T,DH], pre-scaled 1/8
__device__ __half g_Qlo[(size_t)B_ * H_ * T_ * DH_];
__device__ __half g_Khi[(size_t)B_ * H_ * TP_ * DH_];  // rows >= cnt (block cover) zeroed
__device__ __half g_Klo[(size_t)B_ * H_ * TP_ * DH_];
__device__ __half g_Vhi[(size_t)B_ * H_ * TP_ * DH_];
__device__ __half g_Vlo[(size_t)B_ * H_ * TP_ * DH_];
__device__ int   g_act[B_ * TP_];
__device__ int   g_cnt[B_];

// ---------------- helpers ----------------------------------------------------
__device__ __forceinline__ uint32_t smem_u32(const void* p) {
    uint32_t a;
    asm("{ .reg .u64 t; cvta.to.shared.u64 t, %1; cvt.u32.u64 %0, t; }" : "=r"(a) : "l"(p));
    return a;
}
#define CP_ASYNC16(dst, src) \
    asm volatile("cp.async.cg.shared.global [%0], [%1], 16;" :: "r"(dst), "l"(src))
#define CP_COMMIT() asm volatile("cp.async.commit_group;" ::: "memory")

__device__ __forceinline__ void mma_f16(float* c,
        uint32_t a0, uint32_t a1, uint32_t a2, uint32_t a3,
        uint32_t b0, uint32_t b1) {
    asm volatile("mma.sync.aligned.m16n8k16.row.col.f32.f16.f16.f32 "
        "{%0,%1,%2,%3}, {%4,%5,%6,%7}, {%8,%9}, {%0,%1,%2,%3};"
        : "+f"(c[0]), "+f"(c[1]), "+f"(c[2]), "+f"(c[3])
        : "r"(a0), "r"(a1), "r"(a2), "r"(a3), "r"(b0), "r"(b1));
}
__device__ __forceinline__ void ldsm_x4(uint32_t* r, uint32_t addr) {
    asm volatile("ldmatrix.sync.aligned.m8n8.x4.shared.b16 {%0,%1,%2,%3}, [%4];"
        : "=r"(r[0]), "=r"(r[1]), "=r"(r[2]), "=r"(r[3]) : "r"(addr));
}
__device__ __forceinline__ void ldsm_x4t(uint32_t* r, uint32_t addr) {
    asm volatile("ldmatrix.sync.aligned.m8n8.x4.trans.shared.b16 {%0,%1,%2,%3}, [%4];"
        : "=r"(r[0]), "=r"(r[1]), "=r"(r[2]), "=r"(r[3]) : "r"(addr));
}
__device__ __forceinline__ uint32_t packh2(__half x, __half y) {
    __half2 v = __halves2half2(x, y);
    return *(uint32_t*)&v;
}

// ---------------- 1) fused weight fp16 conversion + hs/pool fp16 -------------
#define W4_ (D_ * D_ / 4)
#define HS4_ (B_ * TP_ * D_ / 4)
__global__ void prep_kernel(const float* __restrict__ hs,
                            const float* __restrict__ Wq,
                            const float* __restrict__ Wk,
                            const float* __restrict__ Wv) {
    int p = blockIdx.x * blockDim.x + threadIdx.x;
    if (p < 3 * W4_) {
        const float* src;
        __half* dst;
        int seg = p / W4_, off = p - seg * W4_;
        if (seg == 0)      { src = Wq; dst = g_Wq; }
        else if (seg == 1) { src = Wk; dst = g_Wk; }
        else               { src = Wv; dst = g_Wv; }
        float4 v = ((const float4*)src)[off];
        ushort4 h;
        h.x = __half_as_ushort(__float2half_rn(v.x));
        h.y = __half_as_ushort(__float2half_rn(v.y));
        h.z = __half_as_ushort(__float2half_rn(v.z));
        h.w = __half_as_ushort(__float2half_rn(v.w));
        ((ushort4*)dst)[off] = h;
        return;
    }
    p -= 3 * W4_;
    int d4  = p & 255;
    int row = p >> 8;
    const float4* src = (const float4*)hs;
    size_t base = (size_t)row * (KP_ * 256) + d4;
    float4 s[4];
    #pragma unroll
    for (int r = 0; r < 4; r++) s[r] = src[base + r * 256];
    #pragma unroll
    for (int r = 0; r < 4; r++) {
        ushort4 h;
        h.x = __half_as_ushort(__float2half_rn(s[r].x));
        h.y = __half_as_ushort(__float2half_rn(s[r].y));
        h.z = __half_as_ushort(__float2half_rn(s[r].z));
        h.w = __half_as_ushort(__float2half_rn(s[r].w));
        ((ushort4*)g_hs)[base + r * 256] = h;
    }
    ushort4 h;
    h.x = __half_as_ushort(__float2half_rn((s[0].x + s[1].x + s[2].x + s[3].x) * 0.25f));
    h.y = __half_as_ushort(__float2half_rn((s[0].y + s[1].y + s[2].y + s[3].y) * 0.25f));
    h.z = __half_as_ushort(__float2half_rn((s[0].z + s[1].z + s[2].z + s[3].z) * 0.25f));
    h.w = __half_as_ushort(__float2half_rn((s[0].w + s[1].w + s[2].w + s[3].w) * 0.25f));
    ((ushort4*)g_pool)[p] = h;
}

// ---------------- 2) mask -> compacted list (ballot scan, 2 barriers) --------
__global__ void mask_kernel(const int* __restrict__ am) {
    __shared__ int wsum[32];
    int b = blockIdx.x, tt = threadIdx.x;
    int lane = tt & 31, w = tt >> 5;
    const int* m = am + b * T_ + tt * KP_;
    int s = m[0] + m[1] + m[2] + m[3];
    int act = (s == 0) ? 1 : 0;
    unsigned bal = __ballot_sync(0xffffffffu, act);
    int wpre = __popc(bal & ((1u << lane) - 1u));
    if (lane == 31) wsum[w] = __popc(bal);
    __syncthreads();
    if (w == 0) {
        int v = wsum[lane];
        #pragma unroll
        for (int off = 1; off < 32; off <<= 1) {
            int u = __shfl_up_sync(0xffffffffu, v, off);
            if (lane >= off) v += u;
        }
        wsum[lane] = v;
    }
    __syncthreads();
    int total = wsum[31];
    int pre = (w ? wsum[w - 1] : 0) + wpre;
    if (total == 0) {
        g_act[b * TP_ + tt] = tt;
        if (tt == 0) g_cnt[b] = TP_;
    } else {
        if (act) g_act[b * TP_ + pre] = tt;
        if (tt >= total) g_act[b * TP_ + tt] = 0;
        if (tt == 0) g_cnt[b] = total;
    }
}

// ---------------- 3) fused fp16 projection GEMM (Q + KV, no split-K) ---------
#define RS_ 144
#define ARR_BYTES (128 * RS_)        // 18432
#define STAGE_BYTES (2 * ARR_BYTES)  // 36864
#define SMEM_GEMM (2 * STAGE_BYTES)  // 73728

__global__ void __launch_bounds__(256, 2)
gemm_fused_kernel(const float* __restrict__ bq_,
                  const float* __restrict__ bk_,
                  const float* __restrict__ bv_)
{
    extern __shared__ char smc[];
    const uint32_t sb = smem_u32(smc);
    const int tid = threadIdx.x;
    const int wid = tid >> 5, lane = tid & 31;

    int mode, bn, bm, batch = 0, sel = 0, cnt = 0;
    const __half *A, *W;
    const float* bias;
    if (blockIdx.x < 512) {
        mode = 0;
        bn = (blockIdx.x & 7) * 128;
        bm = (blockIdx.x >> 3) * 128;
        A = g_hs; W = g_Wq; bias = bq_;
    } else {
        mode = 1;
        int r = blockIdx.x - 512;
        bn = (r & 7) * 128;
        bm = ((r >> 3) & 7) * 128;
        int z = r >> 6;
        batch = z & 1;
        sel = z >> 1;
        cnt = g_cnt[batch];
        if (bm >= cnt) return;
        A = g_pool;
        W = sel ? g_Wv : g_Wk;
        bias = sel ? bv_ : bk_;
    }
    const int NK = D_ / 64;

    auto load_stage = [&](int kt, int stage) {
        const uint32_t sbase = sb + stage * STAGE_BYTES;
        const int koff = kt * 64;
        #pragma unroll
        for (int i = 0; i < 8; i++) {
            int idx = tid + i * 256;
            int arr = idx >> 10;
            int r = (idx >> 3) & 127;
            int c = idx & 7;
            const __half* src;
            if (arr == 0) {
                size_t row;
                if (mode == 0) row = (size_t)(bm + r);
                else row = (size_t)batch * TP_ + g_act[batch * TP_ + bm + r];
                src = A + row * D_ + koff + c * 8;
            } else {
                src = W + (size_t)(bn + r) * D_ + koff + c * 8;
            }
            CP_ASYNC16(sbase + arr * ARR_BYTES + r * RS_ + c * 16, src);
        }
        CP_COMMIT();
    };

    float acc[2][8][4];
    #pragma unroll
    for (int mt = 0; mt < 2; mt++)
        #pragma unroll
        for (int nt = 0; nt < 8; nt++)
            #pragma unroll
            for (int j = 0; j < 4; j++) acc[mt][nt][j] = 0.0f;

    const int wm = (wid & 3) * 32;
    const int wn = (wid >> 2) * 64;

    const int arw = (lane & 7) + ((lane >> 3) & 1) * 8;
    const int akh = lane >> 4;
    const int brw = (lane & 7) + (lane >> 4) * 8;
    const int bkh = (lane >> 3) & 1;
    const uint32_t aoff = (uint32_t)((wm + arw) * RS_ + akh * 16);
    const uint32_t boff = (uint32_t)(ARR_BYTES + (wn + brw) * RS_ + bkh * 16);

    load_stage(0, 0);

    for (int kt = 0; kt < NK; kt++) {
        if (kt + 1 < NK) {
            load_stage(kt + 1, (kt + 1) & 1);
            asm volatile("cp.async.wait_group 1;" ::: "memory");
        } else {
            asm volatile("cp.async.wait_group 0;" ::: "memory");
        }
        __syncthreads();

        const uint32_t st = sb + (kt & 1) * STAGE_BYTES;
        const uint32_t aB = st + aoff;
        const uint32_t bB = st + boff;

        #pragma unroll
        for (int j = 0; j < 4; j++) {
            uint32_t af[2][4];
            ldsm_x4(af[0], aB + j * 32);
            ldsm_x4(af[1], aB + 16 * RS_ + j * 32);
            #pragma unroll
            for (int np = 0; np < 4; np++) {
                uint32_t bw[4];
                ldsm_x4(bw, bB + np * 16 * RS_ + j * 32);
                #pragma unroll
                for (int s = 0; s < 2; s++) {
                    const int nt = 2 * np + s;
                    #pragma unroll
                    for (int mt = 0; mt < 2; mt++)
                        mma_f16(acc[mt][nt], af[mt][0], af[mt][1], af[mt][2], af[mt][3], bw[2*s], bw[2*s+1]);
                }
            }
        }
        __syncthreads();
    }

    // ---- epilogue: + bias, fp16 hi/lo split, head-major scatter ----
    const int lr = lane >> 2;
    const int lc = (lane & 3) * 2;
    __half* outh = sel ? g_Vhi : g_Khi;
    __half* outl = sel ? g_Vlo : g_Klo;
    #pragma unroll
    for (int nt = 0; nt < 8; nt++) {
        int c0 = bn + wn + (nt >> 1) * 16 + (nt & 1) * 8 + lc;
        int h = c0 >> 6, d0 = c0 & 63;
        float2 b2 = *(const float2*)(bias + c0);
        #pragma unroll
        for (int mt = 0; mt < 2; mt++) {
            int m0 = bm + wm + mt * 16 + lr;
            #pragma unroll
            for (int half = 0; half < 2; half++) {
                int m = m0 + half * 8;
                if (mode == 0) {
                    int b = m >> 12, ls = m & (T_ - 1);
                    size_t dst = ((size_t)(b * H_ + h) * T_ + ls) * DH_ + d0;
                    float sx = (acc[mt][nt][2 * half + 0] + b2.x) * 0.125f;
                    float sy = (acc[mt][nt][2 * half + 1] + b2.y) * 0.125f;
                    __half hx = __float2half_rn(sx), hy = __float2half_rn(sy);
                    __half lx = __float2half_rn(sx - __half2float(hx));
                    __half ly = __float2half_rn(sy - __half2float(hy));
                    *(uint32_t*)(g_Qhi + dst) = packh2(hx, hy);
                    *(uint32_t*)(g_Qlo + dst) = packh2(lx, ly);
                } else {
                    size_t dst = ((size_t)(batch * H_ + h) * TP_ + m) * DH_ + d0;
                    float sx = acc[mt][nt][2 * half + 0] + b2.x;
                    float sy = acc[mt][nt][2 * half + 1] + b2.y;
                    if (m >= cnt) { sx = 0.0f; sy = 0.0f; }
                    __half hx = __float2half_rn(sx), hy = __float2half_rn(sy);
                    __half lx = __float2half_rn(sx - __half2float(hx));
                    __half ly = __float2half_rn(sy - __half2float(hy));
                    *(uint32_t*)(outh + dst) = packh2(hx, hy);
                    *(uint32_t*)(outl + dst) = packh2(lx, ly);
                }
            }
        }
    }
}

// ---------------- 4) fp16 flash attention (64 q / block, 4 CTAs/SM) ----------
// Scores 3-pass (QhKh+QhKl+QlKh); P@V 2-pass (PhVh+PhVl) — P fp16 quantization
// adds ~2.4e-4 rel err in quadrature, total ~4.2e-4 (threshold 1e-3).
#define ATS 144
#define AARR (64 * ATS)      // 9216
#define SM_KH (2 * AARR)
#define SM_VH (4 * AARR)
#define SMEM_ATTN (6 * AARR) // 55296

__global__ void __launch_bounds__(128, 4)
attn_kernel(float* __restrict__ out)
{
    extern __shared__ char smc[];
    const uint32_t sb = smem_u32(smc);
    const int tid = threadIdx.x, wid = tid >> 5, lane = tid & 31;
    const int b = blockIdx.z, h = blockIdx.y, q0 = blockIdx.x * 64;
    const int cnt = g_cnt[b];
    const int ntiles = (cnt + 63) >> 6;

    const __half* Qhp = g_Qhi + ((size_t)(b * H_ + h) * T_ + q0) * DH_;
    const __half* Qlp = g_Qlo + ((size_t)(b * H_ + h) * T_ + q0) * DH_;
    const size_t kvoff = (size_t)(b * H_ + h) * TP_ * DH_;
    const __half* kvsrc[4] = { g_Khi + kvoff, g_Klo + kvoff,
                               g_Vhi + kvoff, g_Vlo + kvoff };

    #pragma unroll
    for (int i = 0; i < 8; i++) {
        int idx = tid + i * 128;
        int arr = idx >> 9, r = (idx >> 3) & 63, c = idx & 7;
        const __half* src = (arr ? Qlp : Qhp) + (size_t)r * DH_ + c * 8;
        CP_ASYNC16(sb + arr * AARR + r * ATS + c * 16, src);
    }
    CP_COMMIT();

    float acc[8][4];
    #pragma unroll
    for (int nt = 0; nt < 8; nt++)
        #pragma unroll
        for (int j = 0; j < 4; j++) acc[nt][j] = 0.0f;
    float mrow[2] = { -1e30f, -1e30f };
    float lrow[2] = { 0.0f, 0.0f };

    const int lr = lane >> 2, lq = lane & 3;
    const int arw = (lane & 7) + ((lane >> 3) & 1) * 8;
    const int akh = lane >> 4;
    const int brw = (lane & 7) + (lane >> 4) * 8;
    const int bkh = (lane >> 3) & 1;
    const int vrw = (lane & 7) + ((lane >> 3) & 1) * 8;
    const int vc16 = (lane >> 4) * 16;

    const uint32_t qbase = sb + (wid * 16 + arw) * ATS + akh * 16;
    const uint32_t kbase = sb + SM_KH + brw * ATS + bkh * 16;
    const uint32_t vbase = sb + SM_VH + vrw * ATS + vc16;

    for (int t = 0; t < ntiles; t++) {
        const int kb = t * 64;
        #pragma unroll
        for (int i = 0; i < 16; i++) {
            int idx = tid + i * 128;
            int arr = idx >> 9, r = (idx >> 3) & 63, c = idx & 7;
            CP_ASYNC16(sb + SM_KH + arr * AARR + r * ATS + c * 16,
                       kvsrc[arr] + (size_t)(kb + r) * DH_ + c * 8);
        }
        CP_COMMIT();
        asm volatile("cp.async.wait_group 0;" ::: "memory");
        __syncthreads();

        // ---- scores: 3-pass QhKh + QhKl + QlKh ----
        float sc[8][4];
        #pragma unroll
        for (int nt = 0; nt < 8; nt++)
            #pragma unroll
            for (int j = 0; j < 4; j++) sc[nt][j] = 0.0f;
        #pragma unroll
        for (int j = 0; j < 4; j++) {
            uint32_t qh[4], ql[4];
            ldsm_x4(qh, qbase + j * 32);
            ldsm_x4(ql, qbase + AARR + j * 32);
            #pragma unroll
            for (int np = 0; np < 4; np++) {
                uint32_t kh4[4], kl4[4];
                ldsm_x4(kh4, kbase + np * 16 * ATS + j * 32);
                ldsm_x4(kl4, kbase + AARR + np * 16 * ATS + j * 32);
                #pragma unroll
                for (int s = 0; s < 2; s++) {
                    const int nt = 2 * np + s;
                    mma_f16(sc[nt], qh[0], qh[1], qh[2], qh[3], kh4[2*s], kh4[2*s+1]);
                    mma_f16(sc[nt], qh[0], qh[1], qh[2], qh[3], kl4[2*s], kl4[2*s+1]);
                    mma_f16(sc[nt], ql[0], ql[1], ql[2], ql[3], kh4[2*s], kh4[2*s+1]);
                }
            }
        }

        #pragma unroll
        for (int nt = 0; nt < 8; nt++) {
            int key = kb + nt * 8 + lq * 2;
            if (key >= cnt)     { sc[nt][0] = -1e30f; sc[nt][2] = -1e30f; }
            if (key + 1 >= cnt) { sc[nt][1] = -1e30f; sc[nt][3] = -1e30f; }
        }

        // ---- online softmax ----
        float tm0 = -1e30f, tm1 = -1e30f;
        #pragma unroll
        for (int nt = 0; nt < 8; nt++) {
            tm0 = fmaxf(tm0, fmaxf(sc[nt][0], sc[nt][1]));
            tm1 = fmaxf(tm1, fmaxf(sc[nt][2], sc[nt][3]));
        }
        tm0 = fmaxf(tm0, __shfl_xor_sync(0xffffffffu, tm0, 1));
        tm0 = fmaxf(tm0, __shfl_xor_sync(0xffffffffu, tm0, 2));
        tm1 = fmaxf(tm1, __shfl_xor_sync(0xffffffffu, tm1, 1));
        tm1 = fmaxf(tm1, __shfl_xor_sync(0xffffffffu, tm1, 2));
        const float mn0 = fmaxf(mrow[0], tm0);
        const float mn1 = fmaxf(mrow[1], tm1);
        const float al0 = __expf(mrow[0] - mn0);
        const float al1 = __expf(mrow[1] - mn1);

        uint32_t pAh[4][4];
        float ts0 = 0.0f, ts1 = 0.0f;
        #pragma unroll
        for (int nt = 0; nt < 8; nt++) {
            float p0 = __expf(sc[nt][0] - mn0);
            float p1 = __expf(sc[nt][1] - mn0);
            float p2 = __expf(sc[nt][2] - mn1);
            float p3 = __expf(sc[nt][3] - mn1);
            ts0 += p0 + p1;
            ts1 += p2 + p3;
            const int j = nt >> 1, o = (nt & 1) * 2;
            pAh[j][o]     = packh2(__float2half_rn(p0), __float2half_rn(p1));
            pAh[j][o + 1] = packh2(__float2half_rn(p2), __float2half_rn(p3));
        }
        ts0 += __shfl_xor_sync(0xffffffffu, ts0, 1);
        ts0 += __shfl_xor_sync(0xffffffffu, ts0, 2);
        ts1 += __shfl_xor_sync(0xffffffffu, ts1, 1);
        ts1 += __shfl_xor_sync(0xffffffffu, ts1, 2);
        lrow[0] = lrow[0] * al0 + ts0;
        lrow[1] = lrow[1] * al1 + ts1;
        mrow[0] = mn0;
        mrow[1] = mn1;
        #pragma unroll
        for (int nt = 0; nt < 8; nt++) {
            acc[nt][0] *= al0; acc[nt][1] *= al0;
            acc[nt][2] *= al1; acc[nt][3] *= al1;
        }

        // ---- P @ V : 2-pass PhVh + PhVl ----
        #pragma unroll
        for (int j = 0; j < 4; j++) {
            #pragma unroll
            for (int np = 0; np < 4; np++) {
                uint32_t vh4[4], vl4[4];
                ldsm_x4t(vh4, vbase + (j * 16) * ATS + np * 32);
                ldsm_x4t(vl4, vbase + AARR + (j * 16) * ATS + np * 32);
                #pragma unroll
                for (int s = 0; s < 2; s++) {
                    const int nt = 2 * np + s;
                    mma_f16(acc[nt], pAh[j][0], pAh[j][1], pAh[j][2], pAh[j][3], vh4[2*s], vh4[2*s+1]);
                    mma_f16(acc[nt], pAh[j][0], pAh[j][1], pAh[j][2], pAh[j][3], vl4[2*s], vl4[2*s+1]);
                }
            }
        }
        __syncthreads();
    }

    const float inv0 = 1.0f / lrow[0];
    const float inv1 = 1.0f / lrow[1];
    const int row0 = q0 + wid * 16 + lr;
    #pragma unroll
    for (int nt = 0; nt < 8; nt++) {
        int dh = nt * 8 + lq * 2;
        float2 o;
        o.x = acc[nt][0] * inv0; o.y = acc[nt][1] * inv0;
        *(float2*)(out + ((size_t)b * T_ + row0) * D_ + h * DH_ + dh) = o;
        o.x = acc[nt][2] * inv1; o.y = acc[nt][3] * inv1;
        *(float2*)(out + ((size_t)b * T_ + row0 + 8) * D_ + h * DH_ + dh) = o;
    }
}

// ---------------- launch -----------------------------------------------------
extern "C" void kernel_launch(void* const* d_in, const int* in_sizes, int n_in,
                              void* d_out, int out_size) {
    const float* hs = (const float*)d_in[0];
    const int*   am = (const int*)d_in[1];
    const float* Wq = (const float*)d_in[2];
    const float* bq = (const float*)d_in[3];
    const float* Wk = (const float*)d_in[4];
    const float* bk = (const float*)d_in[5];
    const float* Wv = (const float*)d_in[6];
    const float* bv = (const float*)d_in[7];
    float* out = (float*)d_out;

    cudaFuncSetAttribute(gemm_fused_kernel, cudaFuncAttributeMaxDynamicSharedMemorySize, SMEM_GEMM);
    cudaFuncSetAttribute(attn_kernel, cudaFuncAttributeMaxDynamicSharedMemorySize, SMEM_ATTN);

    prep_kernel<<<(3 * W4_ + HS4_) / 256, 256>>>(hs, Wq, Wk, Wv);
    mask_kernel<<<B_, TP_>>>(am);
    gemm_fused_kernel<<<512 + 256, 256, SMEM_GEMM>>>(bq, bk, bv);
    attn_kernel<<<dim3(T_ / 64, H_, B_), 128, SMEM_ATTN>>>(out);
}

// round 17
// speedup vs baseline: 1.2858x; 1.1750x over previous
#include <cuda_runtime.h>
#include <cuda_fp16.h>
#include <cstdint>

#define B_  2
#define T_  4096
#define D_  1024
#define H_  16
#define DH_ 64
#define KP_ 4
#define TP_ 1024

// ---------------- scratch (device globals; no allocations allowed) ----------
__device__ __half g_hs[(size_t)B_ * T_ * D_];
__device__ __half g_pool[B_ * TP_ * D_];
__device__ __half g_Wq[D_ * D_], g_Wk[D_ * D_], g_Wv[D_ * D_];
__device__ __half g_Q[(size_t)B_ * H_ * T_ * DH_];    // [B,H,T,DH], pre-scaled 1/8
__device__ __half g_K[(size_t)B_ * H_ * TP_ * DH_];   // rows >= cnt (block cover) zeroed
__device__ __half g_V[(size_t)B_ * H_ * TP_ * DH_];
__device__ int   g_act[B_ * TP_];
__device__ int   g_cnt[B_];

// ---------------- helpers ----------------------------------------------------
__device__ __forceinline__ uint32_t smem_u32(const void* p) {
    uint32_t a;
    asm("{ .reg .u64 t; cvta.to.shared.u64 t, %1; cvt.u32.u64 %0, t; }" : "=r"(a) : "l"(p));
    return a;
}
#define CP_ASYNC16(dst, src) \
    asm volatile("cp.async.cg.shared.global [%0], [%1], 16;" :: "r"(dst), "l"(src))
#define CP_COMMIT() asm volatile("cp.async.commit_group;" ::: "memory")

__device__ __forceinline__ void mma_f16(float* c,
        uint32_t a0, uint32_t a1, uint32_t a2, uint32_t a3,
        uint32_t b0, uint32_t b1) {
    asm volatile("mma.sync.aligned.m16n8k16.row.col.f32.f16.f16.f32 "
        "{%0,%1,%2,%3}, {%4,%5,%6,%7}, {%8,%9}, {%0,%1,%2,%3};"
        : "+f"(c[0]), "+f"(c[1]), "+f"(c[2]), "+f"(c[3])
        : "r"(a0), "r"(a1), "r"(a2), "r"(a3), "r"(b0), "r"(b1));
}
__device__ __forceinline__ void ldsm_x4(uint32_t* r, uint32_t addr) {
    asm volatile("ldmatrix.sync.aligned.m8n8.x4.shared.b16 {%0,%1,%2,%3}, [%4];"
        : "=r"(r[0]), "=r"(r[1]), "=r"(r[2]), "=r"(r[3]) : "r"(addr));
}
__device__ __forceinline__ void ldsm_x4t(uint32_t* r, uint32_t addr) {
    asm volatile("ldmatrix.sync.aligned.m8n8.x4.trans.shared.b16 {%0,%1,%2,%3}, [%4];"
        : "=r"(r[0]), "=r"(r[1]), "=r"(r[2]), "=r"(r[3]) : "r"(addr));
}
__device__ __forceinline__ uint32_t packh2(__half x, __half y) {
    __half2 v = __halves2half2(x, y);
    return *(uint32_t*)&v;
}

// ---------------- 1) fused weight fp16 conversion + hs/pool fp16 -------------
#define W4_ (D_ * D_ / 4)
#define HS4_ (B_ * TP_ * D_ / 4)
__global__ void prep_kernel(const float* __restrict__ hs,
                            const float* __restrict__ Wq,
                            const float* __restrict__ Wk,
                            const float* __restrict__ Wv) {
    int p = blockIdx.x * blockDim.x + threadIdx.x;
    if (p < 3 * W4_) {
        const float* src;
        __half* dst;
        int seg = p / W4_, off = p - seg * W4_;
        if (seg == 0)      { src = Wq; dst = g_Wq; }
        else if (seg == 1) { src = Wk; dst = g_Wk; }
        else               { src = Wv; dst = g_Wv; }
        float4 v = ((const float4*)src)[off];
        ushort4 h;
        h.x = __half_as_ushort(__float2half_rn(v.x));
        h.y = __half_as_ushort(__float2half_rn(v.y));
        h.z = __half_as_ushort(__float2half_rn(v.z));
        h.w = __half_as_ushort(__float2half_rn(v.w));
        ((ushort4*)dst)[off] = h;
        return;
    }
    p -= 3 * W4_;
    int d4  = p & 255;
    int row = p >> 8;
    const float4* src = (const float4*)hs;
    size_t base = (size_t)row * (KP_ * 256) + d4;
    float4 s[4];
    #pragma unroll
    for (int r = 0; r < 4; r++) s[r] = src[base + r * 256];
    #pragma unroll
    for (int r = 0; r < 4; r++) {
        ushort4 h;
        h.x = __half_as_ushort(__float2half_rn(s[r].x));
        h.y = __half_as_ushort(__float2half_rn(s[r].y));
        h.z = __half_as_ushort(__float2half_rn(s[r].z));
        h.w = __half_as_ushort(__float2half_rn(s[r].w));
        ((ushort4*)g_hs)[base + r * 256] = h;
    }
    ushort4 h;
    h.x = __half_as_ushort(__float2half_rn((s[0].x + s[1].x + s[2].x + s[3].x) * 0.25f));
    h.y = __half_as_ushort(__float2half_rn((s[0].y + s[1].y + s[2].y + s[3].y) * 0.25f));
    h.z = __half_as_ushort(__float2half_rn((s[0].z + s[1].z + s[2].z + s[3].z) * 0.25f));
    h.w = __half_as_ushort(__float2half_rn((s[0].w + s[1].w + s[2].w + s[3].w) * 0.25f));
    ((ushort4*)g_pool)[p] = h;
}

// ---------------- 2) mask -> compacted list (ballot scan, 2 barriers) --------
__global__ void mask_kernel(const int* __restrict__ am) {
    __shared__ int wsum[32];
    int b = blockIdx.x, tt = threadIdx.x;
    int lane = tt & 31, w = tt >> 5;
    const int* m = am + b * T_ + tt * KP_;
    int s = m[0] + m[1] + m[2] + m[3];
    int act = (s == 0) ? 1 : 0;
    unsigned bal = __ballot_sync(0xffffffffu, act);
    int wpre = __popc(bal & ((1u << lane) - 1u));
    if (lane == 31) wsum[w] = __popc(bal);
    __syncthreads();
    if (w == 0) {
        int v = wsum[lane];
        #pragma unroll
        for (int off = 1; off < 32; off <<= 1) {
            int u = __shfl_up_sync(0xffffffffu, v, off);
            if (lane >= off) v += u;
        }
        wsum[lane] = v;
    }
    __syncthreads();
    int total = wsum[31];
    int pre = (w ? wsum[w - 1] : 0) + wpre;
    if (total == 0) {
        g_act[b * TP_ + tt] = tt;
        if (tt == 0) g_cnt[b] = TP_;
    } else {
        if (act) g_act[b * TP_ + pre] = tt;
        if (tt >= total) g_act[b * TP_ + tt] = 0;
        if (tt == 0) g_cnt[b] = total;
    }
}

// ---------------- 3) fused fp16 projection GEMM (Q + KV) ---------------------
#define RS_ 144
#define ARR_BYTES (128 * RS_)        // 18432
#define STAGE_BYTES (2 * ARR_BYTES)  // 36864
#define SMEM_GEMM (2 * STAGE_BYTES)  // 73728

__global__ void __launch_bounds__(256, 2)
gemm_fused_kernel(const float* __restrict__ bq_,
                  const float* __restrict__ bk_,
                  const float* __restrict__ bv_)
{
    extern __shared__ char smc[];
    const uint32_t sb = smem_u32(smc);
    const int tid = threadIdx.x;
    const int wid = tid >> 5, lane = tid & 31;

    int mode, bn, bm, batch = 0, sel = 0, cnt = 0;
    const __half *A, *W;
    const float* bias;
    if (blockIdx.x < 512) {
        mode = 0;
        bn = (blockIdx.x & 7) * 128;
        bm = (blockIdx.x >> 3) * 128;
        A = g_hs; W = g_Wq; bias = bq_;
    } else {
        mode = 1;
        int r = blockIdx.x - 512;
        bn = (r & 7) * 128;
        bm = ((r >> 3) & 7) * 128;
        int z = r >> 6;
        batch = z & 1;
        sel = z >> 1;
        cnt = g_cnt[batch];
        if (bm >= cnt) return;
        A = g_pool;
        W = sel ? g_Wv : g_Wk;
        bias = sel ? bv_ : bk_;
    }
    const int NK = D_ / 64;

    auto load_stage = [&](int kt, int stage) {
        const uint32_t sbase = sb + stage * STAGE_BYTES;
        const int koff = kt * 64;
        #pragma unroll
        for (int i = 0; i < 8; i++) {
            int idx = tid + i * 256;
            int arr = idx >> 10;
            int r = (idx >> 3) & 127;
            int c = idx & 7;
            const __half* src;
            if (arr == 0) {
                size_t row;
                if (mode == 0) row = (size_t)(bm + r);
                else row = (size_t)batch * TP_ + g_act[batch * TP_ + bm + r];
                src = A + row * D_ + koff + c * 8;
            } else {
                src = W + (size_t)(bn + r) * D_ + koff + c * 8;
            }
            CP_ASYNC16(sbase + arr * ARR_BYTES + r * RS_ + c * 16, src);
        }
        CP_COMMIT();
    };

    float acc[2][8][4];
    #pragma unroll
    for (int mt = 0; mt < 2; mt++)
        #pragma unroll
        for (int nt = 0; nt < 8; nt++)
            #pragma unroll
            for (int j = 0; j < 4; j++) acc[mt][nt][j] = 0.0f;

    const int wm = (wid & 3) * 32;
    const int wn = (wid >> 2) * 64;

    const int arw = (lane & 7) + ((lane >> 3) & 1) * 8;
    const int akh = lane >> 4;
    const int brw = (lane & 7) + (lane >> 4) * 8;
    const int bkh = (lane >> 3) & 1;
    const uint32_t aoff = (uint32_t)((wm + arw) * RS_ + akh * 16);
    const uint32_t boff = (uint32_t)(ARR_BYTES + (wn + brw) * RS_ + bkh * 16);

    load_stage(0, 0);

    for (int kt = 0; kt < NK; kt++) {
        if (kt + 1 < NK) {
            load_stage(kt + 1, (kt + 1) & 1);
            asm volatile("cp.async.wait_group 1;" ::: "memory");
        } else {
            asm volatile("cp.async.wait_group 0;" ::: "memory");
        }
        __syncthreads();

        const uint32_t st = sb + (kt & 1) * STAGE_BYTES;
        const uint32_t aB = st + aoff;
        const uint32_t bB = st + boff;

        #pragma unroll
        for (int j = 0; j < 4; j++) {
            uint32_t af[2][4];
            ldsm_x4(af[0], aB + j * 32);
            ldsm_x4(af[1], aB + 16 * RS_ + j * 32);
            #pragma unroll
            for (int np = 0; np < 4; np++) {
                uint32_t bw[4];
                ldsm_x4(bw, bB + np * 16 * RS_ + j * 32);
                #pragma unroll
                for (int s = 0; s < 2; s++) {
                    const int nt = 2 * np + s;
                    #pragma unroll
                    for (int mt = 0; mt < 2; mt++)
                        mma_f16(acc[mt][nt], af[mt][0], af[mt][1], af[mt][2], af[mt][3], bw[2*s], bw[2*s+1]);
                }
            }
        }
        __syncthreads();
    }

    // ---- epilogue: + bias, fp16 convert, head-major scatter ----
    const int lr = lane >> 2;
    const int lc = (lane & 3) * 2;
    __half* outp = (mode == 0) ? g_Q : (sel ? g_V : g_K);
    #pragma unroll
    for (int nt = 0; nt < 8; nt++) {
        int c0 = bn + wn + (nt >> 1) * 16 + (nt & 1) * 8 + lc;
        int h = c0 >> 6, d0 = c0 & 63;
        float2 b2 = *(const float2*)(bias + c0);
        #pragma unroll
        for (int mt = 0; mt < 2; mt++) {
            int m0 = bm + wm + mt * 16 + lr;
            #pragma unroll
            for (int half = 0; half < 2; half++) {
                int m = m0 + half * 8;
                if (mode == 0) {
                    int b = m >> 12, ls = m & (T_ - 1);
                    size_t dst = ((size_t)(b * H_ + h) * T_ + ls) * DH_ + d0;
                    float sx = (acc[mt][nt][2 * half + 0] + b2.x) * 0.125f;
                    float sy = (acc[mt][nt][2 * half + 1] + b2.y) * 0.125f;
                    *(uint32_t*)(outp + dst) = packh2(__float2half_rn(sx), __float2half_rn(sy));
                } else {
                    size_t dst = ((size_t)(batch * H_ + h) * TP_ + m) * DH_ + d0;
                    float sx = acc[mt][nt][2 * half + 0] + b2.x;
                    float sy = acc[mt][nt][2 * half + 1] + b2.y;
                    if (m >= cnt) { sx = 0.0f; sy = 0.0f; }
                    *(uint32_t*)(outp + dst) = packh2(__float2half_rn(sx), __float2half_rn(sy));
                }
            }
        }
    }
}

// ---------------- 4) fp16 flash attention (single-pass, 64 q / block) --------
// Scores Q@K and P@V each single-pass fp16. Error budget (calibrated):
// proj 3.94e-4 (+) scores ~2e-4 (+) V ~1.4e-4 -> ~4.6e-4 (threshold 1e-3).
#define ATS 144
#define AARR (64 * ATS)      // 9216
#define SM_K (AARR)
#define SM_V (2 * AARR)
#define SMEM_ATTN (3 * AARR) // 27648

__global__ void __launch_bounds__(128, 5)
attn_kernel(float* __restrict__ out)
{
    extern __shared__ char smc[];
    const uint32_t sb = smem_u32(smc);
    const int tid = threadIdx.x, wid = tid >> 5, lane = tid & 31;
    const int b = blockIdx.z, h = blockIdx.y, q0 = blockIdx.x * 64;
    const int cnt = g_cnt[b];
    const int ntiles = (cnt + 63) >> 6;

    const __half* Qp = g_Q + ((size_t)(b * H_ + h) * T_ + q0) * DH_;
    const size_t kvoff = (size_t)(b * H_ + h) * TP_ * DH_;
    const __half* Kp = g_K + kvoff;
    const __half* Vp = g_V + kvoff;

    // Q tile: 64 rows x 8 chunks = 512 / 128 thr
    #pragma unroll
    for (int i = 0; i < 4; i++) {
        int idx = tid + i * 128;
        int r = idx >> 3, c = idx & 7;
        CP_ASYNC16(sb + r * ATS + c * 16, Qp + (size_t)r * DH_ + c * 8);
    }
    CP_COMMIT();

    float acc[8][4];
    #pragma unroll
    for (int nt = 0; nt < 8; nt++)
        #pragma unroll
        for (int j = 0; j < 4; j++) acc[nt][j] = 0.0f;
    float mrow[2] = { -1e30f, -1e30f };
    float lrow[2] = { 0.0f, 0.0f };

    const int lr = lane >> 2, lq = lane & 3;
    const int arw = (lane & 7) + ((lane >> 3) & 1) * 8;
    const int akh = lane >> 4;
    const int brw = (lane & 7) + (lane >> 4) * 8;
    const int bkh = (lane >> 3) & 1;
    const int vrw = (lane & 7) + ((lane >> 3) & 1) * 8;
    const int vc16 = (lane >> 4) * 16;

    const uint32_t qbase = sb + (wid * 16 + arw) * ATS + akh * 16;
    const uint32_t kbase = sb + SM_K + brw * ATS + bkh * 16;
    const uint32_t vbase = sb + SM_V + vrw * ATS + vc16;

    for (int t = 0; t < ntiles; t++) {
        const int kb = t * 64;
        // K/V tiles: 2 arrays x 64 rows x 8 chunks = 1024 / 128 thr
        #pragma unroll
        for (int i = 0; i < 8; i++) {
            int idx = tid + i * 128;
            int arr = idx >> 9, r = (idx >> 3) & 63, c = idx & 7;
            const __half* src = (arr ? Vp : Kp) + (size_t)(kb + r) * DH_ + c * 8;
            CP_ASYNC16(sb + SM_K + arr * AARR + r * ATS + c * 16, src);
        }
        CP_COMMIT();
        asm volatile("cp.async.wait_group 0;" ::: "memory");
        __syncthreads();

        // ---- scores: single-pass Q@K ----
        float sc[8][4];
        #pragma unroll
        for (int nt = 0; nt < 8; nt++)
            #pragma unroll
            for (int j = 0; j < 4; j++) sc[nt][j] = 0.0f;
        #pragma unroll
        for (int j = 0; j < 4; j++) {
            uint32_t qf[4];
            ldsm_x4(qf, qbase + j * 32);
            #pragma unroll
            for (int np = 0; np < 4; np++) {
                uint32_t kf[4];
                ldsm_x4(kf, kbase + np * 16 * ATS + j * 32);
                #pragma unroll
                for (int s = 0; s < 2; s++)
                    mma_f16(sc[2 * np + s], qf[0], qf[1], qf[2], qf[3], kf[2*s], kf[2*s+1]);
            }
        }

        #pragma unroll
        for (int nt = 0; nt < 8; nt++) {
            int key = kb + nt * 8 + lq * 2;
            if (key >= cnt)     { sc[nt][0] = -1e30f; sc[nt][2] = -1e30f; }
            if (key + 1 >= cnt) { sc[nt][1] = -1e30f; sc[nt][3] = -1e30f; }
        }

        // ---- online softmax ----
        float tm0 = -1e30f, tm1 = -1e30f;
        #pragma unroll
        for (int nt = 0; nt < 8; nt++) {
            tm0 = fmaxf(tm0, fmaxf(sc[nt][0], sc[nt][1]));
            tm1 = fmaxf(tm1, fmaxf(sc[nt][2], sc[nt][3]));
        }
        tm0 = fmaxf(tm0, __shfl_xor_sync(0xffffffffu, tm0, 1));
        tm0 = fmaxf(tm0, __shfl_xor_sync(0xffffffffu, tm0, 2));
        tm1 = fmaxf(tm1, __shfl_xor_sync(0xffffffffu, tm1, 1));
        tm1 = fmaxf(tm1, __shfl_xor_sync(0xffffffffu, tm1, 2));
        const float mn0 = fmaxf(mrow[0], tm0);
        const float mn1 = fmaxf(mrow[1], tm1);
        const float al0 = __expf(mrow[0] - mn0);
        const float al1 = __expf(mrow[1] - mn1);

        uint32_t pA[4][4];
        float ts0 = 0.0f, ts1 = 0.0f;
        #pragma unroll
        for (int nt = 0; nt < 8; nt++) {
            float p0 = __expf(sc[nt][0] - mn0);
            float p1 = __expf(sc[nt][1] - mn0);
            float p2 = __expf(sc[nt][2] - mn1);
            float p3 = __expf(sc[nt][3] - mn1);
            ts0 += p0 + p1;
            ts1 += p2 + p3;
            const int j = nt >> 1, o = (nt & 1) * 2;
            pA[j][o]     = packh2(__float2half_rn(p0), __float2half_rn(p1));
            pA[j][o + 1] = packh2(__float2half_rn(p2), __float2half_rn(p3));
        }
        ts0 += __shfl_xor_sync(0xffffffffu, ts0, 1);
        ts0 += __shfl_xor_sync(0xffffffffu, ts0, 2);
        ts1 += __shfl_xor_sync(0xffffffffu, ts1, 1);
        ts1 += __shfl_xor_sync(0xffffffffu, ts1, 2);
        lrow[0] = lrow[0] * al0 + ts0;
        lrow[1] = lrow[1] * al1 + ts1;
        mrow[0] = mn0;
        mrow[1] = mn1;
        #pragma unroll
        for (int nt = 0; nt < 8; nt++) {
            acc[nt][0] *= al0; acc[nt][1] *= al0;
            acc[nt][2] *= al1; acc[nt][3] *= al1;
        }

        // ---- P @ V : single-pass ----
        #pragma unroll
        for (int j = 0; j < 4; j++) {
            #pragma unroll
            for (int np = 0; np < 4; np++) {
                uint32_t vf[4];
                ldsm_x4t(vf, vbase + (j * 16) * ATS + np * 32);
                #pragma unroll
                for (int s = 0; s < 2; s++)
                    mma_f16(acc[2 * np + s], pA[j][0], pA[j][1], pA[j][2], pA[j][3], vf[2*s], vf[2*s+1]);
            }
        }
        __syncthreads();
    }

    const float inv0 = 1.0f / lrow[0];
    const float inv1 = 1.0f / lrow[1];
    const int row0 = q0 + wid * 16 + lr;
    #pragma unroll
    for (int nt = 0; nt < 8; nt++) {
        int dh = nt * 8 + lq * 2;
        float2 o;
        o.x = acc[nt][0] * inv0; o.y = acc[nt][1] * inv0;
        *(float2*)(out + ((size_t)b * T_ + row0) * D_ + h * DH_ + dh) = o;
        o.x = acc[nt][2] * inv1; o.y = acc[nt][3] * inv1;
        *(float2*)(out + ((size_t)b * T_ + row0 + 8) * D_ + h * DH_ + dh) = o;
    }
}

// ---------------- launch -----------------------------------------------------
extern "C" void kernel_launch(void* const* d_in, const int* in_sizes, int n_in,
                              void* d_out, int out_size) {
    const float* hs = (const float*)d_in[0];
    const int*   am = (const int*)d_in[1];
    const float* Wq = (const float*)d_in[2];
    const float* bq = (const float*)d_in[3];
    const float* Wk = (const float*)d_in[4];
    const float* bk = (const float*)d_in[5];
    const float* Wv = (const float*)d_in[6];
    const float* bv = (const float*)d_in[7];
    float* out = (float*)d_out;

    cudaFuncSetAttribute(gemm_fused_kernel, cudaFuncAttributeMaxDynamicSharedMemorySize, SMEM_GEMM);
    cudaFuncSetAttribute(attn_kernel, cudaFuncAttributeMaxDynamicSharedMemorySize, SMEM_ATTN);

    prep_kernel<<<(3 * W4_ + HS4_) / 256, 256>>>(hs, Wq, Wk, Wv);
    mask_kernel<<<B_, TP_>>>(am);
    gemm_fused_kernel<<<512 + 256, 256, SMEM_GEMM>>>(bq, bk, bv);
    attn_kernel<<<dim3(T_ / 64, H_, B_), 128, SMEM_ATTN>>>(out);
}